// round 16
// baseline (speedup 1.0000x reference)
#include <cuda_runtime.h>
#include <cuda_fp16.h>
#include <math.h>
#include <cstdint>

#define HIDDEN 2048
#define NHEADS 16
#define HDIM   128
#define BATCH  2
#define SEQ    2048
#define ROWS   (BATCH*SEQ)             // 4096
#define SCALE2 0.12752041986642899f    // (1/sqrt(128)) * log2(e)
#define LOG2E  1.4426950408889634f

// Scratch (allocation-guard-safe), fp16
__device__ __half g_Qh[ROWS*HIDDEN];
__device__ __half g_Kh[ROWS*HIDDEN];
__device__ __half g_Vt[ROWS*HIDDEN];     // transposed: [b][h][d][seq]
__device__ __half g_Ch[ROWS*HIDDEN];     // ctx (attention output)
__device__ __half g_Xh[ROWS*HIDDEN];     // f16 hidden_states
__device__ __half g_Wh[4*HIDDEN*HIDDEN]; // f16 Wq,Wk,Wv,Wo stacked

// ---------------------------------------------------------------------------
// Helpers
// ---------------------------------------------------------------------------
__device__ __forceinline__ float ex2(float x) {
    float r; asm("ex2.approx.f32 %0, %1;" : "=f"(r) : "f"(x)); return r;
}
__device__ __forceinline__ uint32_t smem_u32(const void* p) {
    uint32_t a; asm("{ .reg .u64 t; cvta.to.shared.u64 t, %1; cvt.u32.u64 %0, t; }"
                    : "=r"(a) : "l"(p));
    return a;
}
__device__ __forceinline__ void cpa16(uint32_t dst, const void* src) {
    asm volatile("cp.async.cg.shared.global [%0], [%1], 16;" :: "r"(dst), "l"(src));
}
#define CP_COMMIT()  asm volatile("cp.async.commit_group;" ::: "memory")
#define CP_WAIT(n)   asm volatile("cp.async.wait_group %0;" :: "n"(n) : "memory")

// fp16 MMA, fp32 accumulate: D(16x8) += A(16x16) B(16x8)
__device__ __forceinline__ void mma16(float* c, const unsigned* a, const unsigned* b) {
    asm volatile(
        "mma.sync.aligned.m16n8k16.row.col.f32.f16.f16.f32 "
        "{%0,%1,%2,%3}, {%4,%5,%6,%7}, {%8,%9}, {%0,%1,%2,%3};"
        : "+f"(c[0]), "+f"(c[1]), "+f"(c[2]), "+f"(c[3])
        : "r"(a[0]), "r"(a[1]), "r"(a[2]), "r"(a[3]), "r"(b[0]), "r"(b[1]));
}

// ldmatrix x4: 4 8x8 b16 matrices -> 4 regs/thread
__device__ __forceinline__ void ldsm4(unsigned &r0, unsigned &r1,
                                      unsigned &r2, unsigned &r3, uint32_t addr) {
    asm volatile("ldmatrix.sync.aligned.m8n8.x4.shared.b16 {%0,%1,%2,%3}, [%4];"
        : "=r"(r0), "=r"(r1), "=r"(r2), "=r"(r3) : "r"(addr));
}

// ---------------------------------------------------------------------------
// f32 -> f16 pre-convert
// ---------------------------------------------------------------------------
__global__ void conv_half_kernel(const float* __restrict__ in, __half* __restrict__ out, int n4) {
    int i = blockIdx.x * blockDim.x + threadIdx.x;
    if (i < n4) {
        float4 v = ((const float4*)in)[i];
        __half2 h0 = __floats2half2_rn(v.x, v.y);
        __half2 h1 = __floats2half2_rn(v.z, v.w);
        uint2 o = { *(uint32_t*)&h0, *(uint32_t*)&h1 };
        ((uint2*)out)[i] = o;
    }
}

struct WPtrs { const float* w[4]; };

__global__ void conv_w4_kernel(WPtrs ws, __half* __restrict__ out, int nw4) {
    int i = blockIdx.x * blockDim.x + threadIdx.x;   // over 4*nw4
    int which = i / nw4;
    int off   = i - which * nw4;
    float4 v = ((const float4*)ws.w[which])[off];
    __half2 h0 = __floats2half2_rn(v.x, v.y);
    __half2 h1 = __floats2half2_rn(v.z, v.w);
    uint2 o = { *(uint32_t*)&h0, *(uint32_t*)&h1 };
    ((uint2*)out)[i] = o;
}

// ---------------------------------------------------------------------------
// FP16 mma.sync GEMM with ldmatrix fragment loads (unchanged — proven R13).
// 128x128x64 CTA tile, 4 warps (64x64 warp tile), 3-stage cp.async,
// 2 CTAs/SM. Stacked-N fused QKV; V stored transposed [b][h][d][seq].
// ---------------------------------------------------------------------------
#define GBM 128
#define GBN 128
#define GBK 64
#define ASTH 72
#define STG_BYTES (2*GBM*ASTH*2)            // 36864 B
#define NSTAGE 3
#define GEMM_SMEM (NSTAGE*STG_BYTES)        // 110592 B
#define KCHUNKS (HIDDEN/GBK)                // 32

struct GemmOuts {
    void* out[3];
    const float* bias[3];
};

template<int OUTMODE>
__global__ __launch_bounds__(128, 2) void h16_gemm(
    const __half* __restrict__ A, const __half* __restrict__ W, GemmOuts go)
{
    extern __shared__ char smemc[];
    const uint32_t sbase = smem_u32(smemc);
    const int tid  = threadIdx.x;
    const int lane = tid & 31;
    const int warp = tid >> 5;
    const int g    = lane >> 2;
    const int l4   = lane & 3;
    const int mb   = (warp & 1) * 64;
    const int nb   = (warp >> 1) * 64;
    const int brow = blockIdx.y * GBM;
    const int bnT  = blockIdx.x * GBN;
    const int which = bnT >> 11;
    const int bn    = bnT & 2047;
    const float* bias = go.bias[which];

    const int lrowA = lane & 15;
    const int lcolA = (lane >> 4) * 8;
    const int lrowB = ((lane >> 4) << 3) + (lane & 7);
    const int lcolB = ((lane >> 3) & 1) * 8;

    float acc[4][8][4];
    #pragma unroll
    for (int i = 0; i < 4; i++)
        #pragma unroll
        for (int j = 0; j < 8; j++)
            #pragma unroll
            for (int t = 0; t < 4; t++) acc[i][j][t] = 0.f;

    auto load_stage = [&](int c, int s) {
        const uint32_t dA = sbase + (uint32_t)s * STG_BYTES;
        const uint32_t dB = dA + GBM*ASTH*2;
        const int k0 = c * GBK;
        #pragma unroll
        for (int i = 0; i < 8; i++) {
            int idx = tid + i * 128;
            int row = idx >> 3, kc = (idx & 7) * 8;
            cpa16(dA + (row * ASTH + kc) * 2,
                  &A[(size_t)(brow + row) * HIDDEN + k0 + kc]);
        }
        #pragma unroll
        for (int i = 0; i < 8; i++) {
            int idx = tid + i * 128;
            int row = idx >> 3, kc = (idx & 7) * 8;
            cpa16(dB + (row * ASTH + kc) * 2,
                  &W[(size_t)(bnT + row) * HIDDEN + k0 + kc]);
        }
        CP_COMMIT();
    };

    load_stage(0, 0);
    load_stage(1, 1);

    int s = 0;
    for (int c = 0; c < KCHUNKS; c++) {
        if (c == KCHUNKS - 1) { CP_WAIT(0); } else { CP_WAIT(1); }
        __syncthreads();
        if (c + 2 < KCHUNKS) load_stage(c + 2, (c + 2) % NSTAGE);

        const uint32_t stB = sbase + (uint32_t)s * STG_BYTES;
        const uint32_t aA = stB + ((mb + lrowA) * ASTH + lcolA) * 2;
        const uint32_t aB = stB + GBM*ASTH*2 + ((nb + lrowB) * ASTH + lcolB) * 2;

        #pragma unroll
        for (int ks = 0; ks < GBK; ks += 16) {
            unsigned af[4][4], bf[8][2];
            #pragma unroll
            for (int i = 0; i < 4; i++)
                ldsm4(af[i][0], af[i][1], af[i][2], af[i][3],
                      aA + (i*16*ASTH + ks) * 2);
            #pragma unroll
            for (int jp = 0; jp < 4; jp++)
                ldsm4(bf[2*jp][0], bf[2*jp][1], bf[2*jp+1][0], bf[2*jp+1][1],
                      aB + (jp*16*ASTH + ks) * 2);
            #pragma unroll
            for (int i = 0; i < 4; i++)
                #pragma unroll
                for (int j = 0; j < 8; j++)
                    mma16(acc[i][j], af[i], bf[j]);
        }
        s = (s == NSTAGE - 1) ? 0 : s + 1;
    }

    if (OUTMODE == 1) {
        float* C = (float*)go.out[which];
        #pragma unroll
        for (int i = 0; i < 4; i++) {
            const int r0 = brow + mb + i*16 + g;
            #pragma unroll
            for (int j = 0; j < 8; j++) {
                const int col = bn + nb + j*8 + 2*l4;
                float b0 = bias[col], b1 = bias[col + 1];
                float2 w0 = { acc[i][j][0] + b0, acc[i][j][1] + b1 };
                float2 w1 = { acc[i][j][2] + b0, acc[i][j][3] + b1 };
                *(float2*)&C[(size_t)r0 * HIDDEN + col]       = w0;
                *(float2*)&C[(size_t)(r0 + 8) * HIDDEN + col] = w1;
            }
        }
    } else if (which != 2) {
        __half* C = (__half*)go.out[which];
        #pragma unroll
        for (int i = 0; i < 4; i++) {
            const int r0 = brow + mb + i*16 + g;
            #pragma unroll
            for (int j = 0; j < 8; j++) {
                const int col = bn + nb + j*8 + 2*l4;
                float b0 = bias[col], b1 = bias[col + 1];
                __half2 h0 = __floats2half2_rn(acc[i][j][0] + b0, acc[i][j][1] + b1);
                __half2 h1 = __floats2half2_rn(acc[i][j][2] + b0, acc[i][j][3] + b1);
                *(__half2*)&C[(size_t)r0 * HIDDEN + col]       = h0;
                *(__half2*)&C[(size_t)(r0 + 8) * HIDDEN + col] = h1;
            }
        }
    } else {
        // V: store transposed [b][h][d][seq]
        __half* Vt = (__half*)go.out[2];
        #pragma unroll
        for (int i = 0; i < 4; i++) {
            const int r0 = brow + mb + i*16 + g;      // token
            const int b  = r0 >> 11;
            const int s0 = r0 & 2047;
            #pragma unroll
            for (int j = 0; j < 8; j++) {
                const int col = bn + nb + j*8 + 2*l4; // h*128 + d
                const int hh = col >> 7, d = col & 127;
                float b0 = bias[col], b1 = bias[col + 1];
                size_t base0 = ((size_t)(b*NHEADS + hh)*HDIM + d) * SEQ;
                Vt[base0 + s0]            = __float2half_rn(acc[i][j][0] + b0);
                Vt[base0 + SEQ + s0]      = __float2half_rn(acc[i][j][1] + b1);
                Vt[base0 + s0 + 8]        = __float2half_rn(acc[i][j][2] + b0);
                Vt[base0 + SEQ + s0 + 8]  = __float2half_rn(acc[i][j][3] + b1);
            }
        }
    }
}

// ---------------------------------------------------------------------------
// FP16 flash attention, FlashAttention-2 warp decomposition:
// 8 warps x 16 q-rows each, ALL 128 keys per warp per iteration.
// Softmax is warp-local (quad shuffles only; running m/l in registers).
// P = exp(S) converted IN REGISTERS from accumulator layout to A-fragment
// layout (acc n-tiles 2t,2t+1 -> A-frag k-tile t) — no smem round trip.
// Double-buffered K/V cp.async prefetch; 2 barriers/iteration.
// ---------------------------------------------------------------------------
#define AQ  128
#define AKK 128
#define QWH 136                        // row stride in halves (272 B)
#define TILE_B (AQ*QWH*2)              // 34816 B per tile
#define OQ_B  0
#define OK0_B (TILE_B)
#define OK1_B (2*TILE_B)
#define OV0_B (3*TILE_B)
#define OV1_B (4*TILE_B)
#define ATT_SMEM (5*TILE_B)            // 174080 B

__global__ __launch_bounds__(256, 1) void attn_h16(
    const __half* __restrict__ Q, const __half* __restrict__ K,
    const __half* __restrict__ Vt, const float* __restrict__ mask,
    __half* __restrict__ O)
{
    extern __shared__ char smemc[];
    const uint32_t sbase = smem_u32(smemc);
    __half* sQh = (__half*)(smemc + OQ_B);

    const int tid  = threadIdx.x;
    const int lane = tid & 31;
    const int warp = tid >> 5;          // 0..7
    const int g    = lane >> 2;
    const int l4   = lane & 3;
    const int mb   = warp * 16;         // this warp's 16 q-rows
    const int qt = blockIdx.x, h = blockIdx.y, b = blockIdx.z;
    const size_t base  = (size_t)b * SEQ * HIDDEN + (size_t)h * HDIM;
    const size_t vbase = ((size_t)(b*NHEADS + h)) * HDIM * SEQ;

    const int lrowA = lane & 15;
    const int lcolA = (lane >> 4) * 8;
    const int lrowB = ((lane >> 4) << 3) + (lane & 7);
    const int lcolB = ((lane >> 3) & 1) * 8;

    auto load_k = [&](int kt2, uint32_t dstoff) {
        const uint32_t kdst = sbase + dstoff;
        #pragma unroll
        for (int i = 0; i < 8; i++) {
            int it = tid + i*256;
            int r = it >> 4, c = (it & 15) * 8;
            cpa16(kdst + (r*QWH + c)*2,
                  &K[base + (size_t)(kt2*AKK + r)*HIDDEN + c]);
        }
        CP_COMMIT();
    };
    auto load_v = [&](int kt2, uint32_t dstoff) {
        const uint32_t vdst = sbase + dstoff;
        #pragma unroll
        for (int i = 0; i < 8; i++) {
            int it = tid + i*256;
            int d = it >> 4, c = (it & 15) * 8;
            cpa16(vdst + (d*QWH + c)*2,
                  &Vt[vbase + (size_t)d*SEQ + kt2*AKK + c]);
        }
        CP_COMMIT();
    };

    load_k(0, OK0_B);
    load_v(0, OV0_B);
    for (int it = tid; it < AQ*16; it += 256) {
        int r = it >> 4, c = (it & 15) * 8;
        *(uint4*)&sQh[r*QWH + c] =
            *(const uint4*)&Q[base + (size_t)(qt*AQ + r)*HIDDEN + c];
    }

    // running stats in registers (rows g and g+8 of this warp's block)
    float rM0 = -1e30f, rM1 = -1e30f, rL0 = 0.f, rL1 = 0.f;

    float oacc[16][4];
    #pragma unroll
    for (int j = 0; j < 16; j++)
        #pragma unroll
        for (int t = 0; t < 4; t++) oacc[j][t] = 0.f;

    const uint32_t aQ = sbase + OQ_B + ((mb + lrowA) * QWH + lcolA) * 2;
    const float* mrowb = &mask[(size_t)b*SEQ];

    const int NIT = SEQ/AKK;           // 16
    for (int kt = 0; kt < NIT; kt++) {
        const int cur = kt & 1;
        const uint32_t okb = cur ? OK1_B : OK0_B;
        const uint32_t ovb = cur ? OV1_B : OV0_B;

        CP_WAIT(1);        // K[kt] retired
        __syncthreads();   // (1) K visible; prior-iter K/V reads complete

        if (kt + 1 < NIT) {
            load_k(kt + 1, cur ? OK0_B : OK1_B);
            load_v(kt + 1, cur ? OV0_B : OV1_B);
        }

        // ---- S = Q K^T : warp tile 16 rows x 128 keys
        float sacc[16][4];
        #pragma unroll
        for (int j = 0; j < 16; j++)
            #pragma unroll
            for (int t = 0; t < 4; t++) sacc[j][t] = 0.f;

        const uint32_t aK = sbase + okb + (lrowB * QWH + lcolB) * 2;
        #pragma unroll
        for (int ks = 0; ks < HDIM; ks += 16) {
            unsigned af[4], bf[16][2];
            ldsm4(af[0], af[1], af[2], af[3], aQ + ks * 2);
            #pragma unroll
            for (int jp = 0; jp < 8; jp++)
                ldsm4(bf[2*jp][0], bf[2*jp][1], bf[2*jp+1][0], bf[2*jp+1][1],
                      aK + (jp*16*QWH + ks) * 2);
            #pragma unroll
            for (int j = 0; j < 16; j++)
                mma16(sacc[j], af, bf[j]);
        }

        // ---- scale + mask (log2 domain) + row max (warp-local)
        const float* mrow = mrowb + kt*AKK;
        float mx0 = -1e30f, mx1 = -1e30f;
        #pragma unroll
        for (int j = 0; j < 16; j++) {
            float2 mv = *(const float2*)&mrow[j*8 + 2*l4];
            float m0 = mv.x * LOG2E, m1 = mv.y * LOG2E;
            sacc[j][0] = sacc[j][0]*SCALE2 + m0;
            sacc[j][1] = sacc[j][1]*SCALE2 + m1;
            sacc[j][2] = sacc[j][2]*SCALE2 + m0;
            sacc[j][3] = sacc[j][3]*SCALE2 + m1;
            mx0 = fmaxf(mx0, fmaxf(sacc[j][0], sacc[j][1]));
            mx1 = fmaxf(mx1, fmaxf(sacc[j][2], sacc[j][3]));
        }
        mx0 = fmaxf(mx0, __shfl_xor_sync(0xffffffffu, mx0, 1));
        mx0 = fmaxf(mx0, __shfl_xor_sync(0xffffffffu, mx0, 2));
        mx1 = fmaxf(mx1, __shfl_xor_sync(0xffffffffu, mx1, 1));
        mx1 = fmaxf(mx1, __shfl_xor_sync(0xffffffffu, mx1, 2));

        float mt0 = fmaxf(rM0, mx0), mt1 = fmaxf(rM1, mx1);
        float f0 = ex2(rM0 - mt0), f1 = ex2(rM1 - mt1);
        rM0 = mt0; rM1 = mt1;

        // ---- exp in registers, convert straight to PV A-fragments
        // pf[t] covers keys 16t..16t+15: a0/a1 from n-tile 2t, a2/a3 from 2t+1
        unsigned pf[8][4];
        float ls0 = 0.f, ls1 = 0.f;
        #pragma unroll
        for (int t = 0; t < 8; t++) {
            __half2 a0 = __floats2half2_rn(ex2(sacc[2*t][0]   - mt0),
                                           ex2(sacc[2*t][1]   - mt0));
            __half2 a1 = __floats2half2_rn(ex2(sacc[2*t][2]   - mt1),
                                           ex2(sacc[2*t][3]   - mt1));
            __half2 a2 = __floats2half2_rn(ex2(sacc[2*t+1][0] - mt0),
                                           ex2(sacc[2*t+1][1] - mt0));
            __half2 a3 = __floats2half2_rn(ex2(sacc[2*t+1][2] - mt1),
                                           ex2(sacc[2*t+1][3] - mt1));
            pf[t][0] = *(unsigned*)&a0; pf[t][1] = *(unsigned*)&a1;
            pf[t][2] = *(unsigned*)&a2; pf[t][3] = *(unsigned*)&a3;
            float2 s0 = __half22float2(a0), s2 = __half22float2(a2);
            float2 s1 = __half22float2(a1), s3 = __half22float2(a3);
            ls0 += s0.x + s0.y + s2.x + s2.y;
            ls1 += s1.x + s1.y + s3.x + s3.y;
        }
        ls0 += __shfl_xor_sync(0xffffffffu, ls0, 1);
        ls0 += __shfl_xor_sync(0xffffffffu, ls0, 2);
        ls1 += __shfl_xor_sync(0xffffffffu, ls1, 1);
        ls1 += __shfl_xor_sync(0xffffffffu, ls1, 2);
        rL0 = rL0 * f0 + ls0;
        rL1 = rL1 * f1 + ls1;

        if (kt + 1 < NIT) { CP_WAIT(2); }   // V[kt] retired; K/V[kt+1] in flight
        else              { CP_WAIT(0); }
        __syncthreads();   // (2) V visible

        // ---- rescale O, accumulate P V : 16 rows x 128 d
        #pragma unroll
        for (int j = 0; j < 16; j++) {
            oacc[j][0] *= f0; oacc[j][1] *= f0;
            oacc[j][2] *= f1; oacc[j][3] *= f1;
        }
        const uint32_t aV = sbase + ovb + (lrowB * QWH + lcolB) * 2;
        #pragma unroll
        for (int ks = 0; ks < AKK; ks += 16) {
            unsigned bf[16][2];
            #pragma unroll
            for (int jp = 0; jp < 8; jp++)
                ldsm4(bf[2*jp][0], bf[2*jp][1], bf[2*jp+1][0], bf[2*jp+1][1],
                      aV + (jp*16*QWH + ks) * 2);
            const unsigned* a = pf[ks >> 4];
            #pragma unroll
            for (int j = 0; j < 16; j++)
                mma16(oacc[j], a, bf[j]);
        }
    }

    // normalize + write ctx (f16, [token][hidden] layout); warp-local stats
    float i0 = 1.f / rL0, i1 = 1.f / rL1;
    #pragma unroll
    for (int j = 0; j < 16; j++) {
        int col = j*8 + 2*l4;
        size_t r0 = base + (size_t)(qt*AQ + mb + g    )*HIDDEN + col;
        size_t r1 = base + (size_t)(qt*AQ + mb + g + 8)*HIDDEN + col;
        *(__half2*)&O[r0] = __floats2half2_rn(oacc[j][0]*i0, oacc[j][1]*i0);
        *(__half2*)&O[r1] = __floats2half2_rn(oacc[j][2]*i1, oacc[j][3]*i1);
    }
}

// ---------------------------------------------------------------------------
extern "C" void kernel_launch(void* const* d_in, const int* in_sizes, int n_in,
                              void* d_out, int out_size) {
    const float* X    = (const float*)d_in[0];
    const float* mask = (const float*)d_in[1];
    const float* Wq   = (const float*)d_in[2];
    const float* bq   = (const float*)d_in[3];
    const float* Wk   = (const float*)d_in[4];
    const float* bk   = (const float*)d_in[5];
    const float* Wv   = (const float*)d_in[6];
    const float* bv   = (const float*)d_in[7];
    const float* Wo   = (const float*)d_in[8];
    const float* bo   = (const float*)d_in[9];
    float* out = (float*)d_out;

    __half *qp, *kp, *vtp, *cp, *xh, *wh;
    cudaGetSymbolAddress((void**)&qp,  g_Qh);
    cudaGetSymbolAddress((void**)&kp,  g_Kh);
    cudaGetSymbolAddress((void**)&vtp, g_Vt);
    cudaGetSymbolAddress((void**)&cp,  g_Ch);
    cudaGetSymbolAddress((void**)&xh,  g_Xh);
    cudaGetSymbolAddress((void**)&wh,  g_Wh);

    const int NX4 = ROWS*HIDDEN/4, NW4 = HIDDEN*HIDDEN/4;
    conv_half_kernel<<<(NX4+255)/256, 256>>>(X, xh, NX4);
    WPtrs ws; ws.w[0] = Wq; ws.w[1] = Wk; ws.w[2] = Wv; ws.w[3] = Wo;
    conv_w4_kernel<<<(4*NW4)/256, 256>>>(ws, wh, NW4);

    cudaFuncSetAttribute(h16_gemm<0>, cudaFuncAttributeMaxDynamicSharedMemorySize, GEMM_SMEM);
    cudaFuncSetAttribute(h16_gemm<1>, cudaFuncAttributeMaxDynamicSharedMemorySize, GEMM_SMEM);

    // Fused QKV GEMM (Wq,Wk,Wv stacked in g_Wh)
    GemmOuts qkv;
    qkv.out[0] = qp;  qkv.out[1] = kp;  qkv.out[2] = vtp;
    qkv.bias[0] = bq; qkv.bias[1] = bk; qkv.bias[2] = bv;
    dim3 qkvgrid(3*HIDDEN/GBN, ROWS/GBM);   // (48, 32)
    h16_gemm<0><<<qkvgrid, 128, GEMM_SMEM>>>(xh, wh, qkv);

    cudaFuncSetAttribute(attn_h16, cudaFuncAttributeMaxDynamicSharedMemorySize, (int)ATT_SMEM);
    dim3 agrid(SEQ/AQ, NHEADS, BATCH);  // (16, 16, 2)
    attn_h16<<<agrid, 256, ATT_SMEM>>>(qp, kp, vtp, mask, cp);

    // Output GEMM: Wo rows at offset 3*H*H, f32 out
    GemmOuts og;
    og.out[0] = out; og.out[1] = out; og.out[2] = out;
    og.bias[0] = bo; og.bias[1] = bo; og.bias[2] = bo;
    dim3 ogrid(HIDDEN/GBN, ROWS/GBM);   // (16, 32)
    h16_gemm<1><<<ogrid, 128, GEMM_SMEM>>>(cp, wh + 3*HIDDEN*HIDDEN, og);
}

// round 17
// speedup vs baseline: 1.5370x; 1.5370x over previous
#include <cuda_runtime.h>
#include <cuda_fp16.h>
#include <math.h>
#include <cstdint>

#define HIDDEN 2048
#define NHEADS 16
#define HDIM   128
#define BATCH  2
#define SEQ    2048
#define ROWS   (BATCH*SEQ)             // 4096
#define SCALE2 0.12752041986642899f    // (1/sqrt(128)) * log2(e)
#define LOG2E  1.4426950408889634f

// Scratch (allocation-guard-safe), fp16
__device__ __half g_Qh[ROWS*HIDDEN];
__device__ __half g_Kh[ROWS*HIDDEN];
__device__ __half g_Vt[ROWS*HIDDEN];     // transposed: [b][h][d][seq]
__device__ __half g_Ch[ROWS*HIDDEN];     // ctx (attention output)
__device__ __half g_Xh[ROWS*HIDDEN];     // f16 hidden_states
__device__ __half g_Wh[4*HIDDEN*HIDDEN]; // f16 Wq,Wk,Wv,Wo stacked

// ---------------------------------------------------------------------------
// Helpers
// ---------------------------------------------------------------------------
__device__ __forceinline__ float ex2(float x) {
    float r; asm("ex2.approx.f32 %0, %1;" : "=f"(r) : "f"(x)); return r;
}
__device__ __forceinline__ uint32_t smem_u32(const void* p) {
    uint32_t a; asm("{ .reg .u64 t; cvta.to.shared.u64 t, %1; cvt.u32.u64 %0, t; }"
                    : "=r"(a) : "l"(p));
    return a;
}
__device__ __forceinline__ void cpa16(uint32_t dst, const void* src) {
    asm volatile("cp.async.cg.shared.global [%0], [%1], 16;" :: "r"(dst), "l"(src));
}
#define CP_COMMIT()  asm volatile("cp.async.commit_group;" ::: "memory")
#define CP_WAIT(n)   asm volatile("cp.async.wait_group %0;" :: "n"(n) : "memory")

// fp16 MMA, fp32 accumulate: D(16x8) += A(16x16) B(16x8)
__device__ __forceinline__ void mma16(float* c, const unsigned* a, const unsigned* b) {
    asm volatile(
        "mma.sync.aligned.m16n8k16.row.col.f32.f16.f16.f32 "
        "{%0,%1,%2,%3}, {%4,%5,%6,%7}, {%8,%9}, {%0,%1,%2,%3};"
        : "+f"(c[0]), "+f"(c[1]), "+f"(c[2]), "+f"(c[3])
        : "r"(a[0]), "r"(a[1]), "r"(a[2]), "r"(a[3]), "r"(b[0]), "r"(b[1]));
}

// ldmatrix x4: 4 8x8 b16 matrices -> 4 regs/thread
__device__ __forceinline__ void ldsm4(unsigned &r0, unsigned &r1,
                                      unsigned &r2, unsigned &r3, uint32_t addr) {
    asm volatile("ldmatrix.sync.aligned.m8n8.x4.shared.b16 {%0,%1,%2,%3}, [%4];"
        : "=r"(r0), "=r"(r1), "=r"(r2), "=r"(r3) : "r"(addr));
}

// ---------------------------------------------------------------------------
// f32 -> f16 pre-convert
// ---------------------------------------------------------------------------
__global__ void conv_half_kernel(const float* __restrict__ in, __half* __restrict__ out, int n4) {
    int i = blockIdx.x * blockDim.x + threadIdx.x;
    if (i < n4) {
        float4 v = ((const float4*)in)[i];
        __half2 h0 = __floats2half2_rn(v.x, v.y);
        __half2 h1 = __floats2half2_rn(v.z, v.w);
        uint2 o = { *(uint32_t*)&h0, *(uint32_t*)&h1 };
        ((uint2*)out)[i] = o;
    }
}

struct WPtrs { const float* w[4]; };

__global__ void conv_w4_kernel(WPtrs ws, __half* __restrict__ out, int nw4) {
    int i = blockIdx.x * blockDim.x + threadIdx.x;   // over 4*nw4
    int which = i / nw4;
    int off   = i - which * nw4;
    float4 v = ((const float4*)ws.w[which])[off];
    __half2 h0 = __floats2half2_rn(v.x, v.y);
    __half2 h1 = __floats2half2_rn(v.z, v.w);
    uint2 o = { *(uint32_t*)&h0, *(uint32_t*)&h1 };
    ((uint2*)out)[i] = o;
}

// ---------------------------------------------------------------------------
// FP16 mma.sync GEMM with ldmatrix fragment loads (unchanged — proven R13).
// 128x128x64 CTA tile, 4 warps (64x64 warp tile), 3-stage cp.async,
// 2 CTAs/SM. Stacked-N fused QKV; V stored transposed [b][h][d][seq].
// ---------------------------------------------------------------------------
#define GBM 128
#define GBN 128
#define GBK 64
#define ASTH 72
#define STG_BYTES (2*GBM*ASTH*2)            // 36864 B
#define NSTAGE 3
#define GEMM_SMEM (NSTAGE*STG_BYTES)        // 110592 B
#define KCHUNKS (HIDDEN/GBK)                // 32

struct GemmOuts {
    void* out[3];
    const float* bias[3];
};

template<int OUTMODE>
__global__ __launch_bounds__(128, 2) void h16_gemm(
    const __half* __restrict__ A, const __half* __restrict__ W, GemmOuts go)
{
    extern __shared__ char smemc[];
    const uint32_t sbase = smem_u32(smemc);
    const int tid  = threadIdx.x;
    const int lane = tid & 31;
    const int warp = tid >> 5;
    const int g    = lane >> 2;
    const int l4   = lane & 3;
    const int mb   = (warp & 1) * 64;
    const int nb   = (warp >> 1) * 64;
    const int brow = blockIdx.y * GBM;
    const int bnT  = blockIdx.x * GBN;
    const int which = bnT >> 11;
    const int bn    = bnT & 2047;
    const float* bias = go.bias[which];

    const int lrowA = lane & 15;
    const int lcolA = (lane >> 4) * 8;
    const int lrowB = ((lane >> 4) << 3) + (lane & 7);
    const int lcolB = ((lane >> 3) & 1) * 8;

    float acc[4][8][4];
    #pragma unroll
    for (int i = 0; i < 4; i++)
        #pragma unroll
        for (int j = 0; j < 8; j++)
            #pragma unroll
            for (int t = 0; t < 4; t++) acc[i][j][t] = 0.f;

    auto load_stage = [&](int c, int s) {
        const uint32_t dA = sbase + (uint32_t)s * STG_BYTES;
        const uint32_t dB = dA + GBM*ASTH*2;
        const int k0 = c * GBK;
        #pragma unroll
        for (int i = 0; i < 8; i++) {
            int idx = tid + i * 128;
            int row = idx >> 3, kc = (idx & 7) * 8;
            cpa16(dA + (row * ASTH + kc) * 2,
                  &A[(size_t)(brow + row) * HIDDEN + k0 + kc]);
        }
        #pragma unroll
        for (int i = 0; i < 8; i++) {
            int idx = tid + i * 128;
            int row = idx >> 3, kc = (idx & 7) * 8;
            cpa16(dB + (row * ASTH + kc) * 2,
                  &W[(size_t)(bnT + row) * HIDDEN + k0 + kc]);
        }
        CP_COMMIT();
    };

    load_stage(0, 0);
    load_stage(1, 1);

    int s = 0;
    for (int c = 0; c < KCHUNKS; c++) {
        if (c == KCHUNKS - 1) { CP_WAIT(0); } else { CP_WAIT(1); }
        __syncthreads();
        if (c + 2 < KCHUNKS) load_stage(c + 2, (c + 2) % NSTAGE);

        const uint32_t stB = sbase + (uint32_t)s * STG_BYTES;
        const uint32_t aA = stB + ((mb + lrowA) * ASTH + lcolA) * 2;
        const uint32_t aB = stB + GBM*ASTH*2 + ((nb + lrowB) * ASTH + lcolB) * 2;

        #pragma unroll
        for (int ks = 0; ks < GBK; ks += 16) {
            unsigned af[4][4], bf[8][2];
            #pragma unroll
            for (int i = 0; i < 4; i++)
                ldsm4(af[i][0], af[i][1], af[i][2], af[i][3],
                      aA + (i*16*ASTH + ks) * 2);
            #pragma unroll
            for (int jp = 0; jp < 4; jp++)
                ldsm4(bf[2*jp][0], bf[2*jp][1], bf[2*jp+1][0], bf[2*jp+1][1],
                      aB + (jp*16*ASTH + ks) * 2);
            #pragma unroll
            for (int i = 0; i < 4; i++)
                #pragma unroll
                for (int j = 0; j < 8; j++)
                    mma16(acc[i][j], af[i], bf[j]);
        }
        s = (s == NSTAGE - 1) ? 0 : s + 1;
    }

    if (OUTMODE == 1) {
        float* C = (float*)go.out[which];
        #pragma unroll
        for (int i = 0; i < 4; i++) {
            const int r0 = brow + mb + i*16 + g;
            #pragma unroll
            for (int j = 0; j < 8; j++) {
                const int col = bn + nb + j*8 + 2*l4;
                float b0 = bias[col], b1 = bias[col + 1];
                float2 w0 = { acc[i][j][0] + b0, acc[i][j][1] + b1 };
                float2 w1 = { acc[i][j][2] + b0, acc[i][j][3] + b1 };
                *(float2*)&C[(size_t)r0 * HIDDEN + col]       = w0;
                *(float2*)&C[(size_t)(r0 + 8) * HIDDEN + col] = w1;
            }
        }
    } else if (which != 2) {
        __half* C = (__half*)go.out[which];
        #pragma unroll
        for (int i = 0; i < 4; i++) {
            const int r0 = brow + mb + i*16 + g;
            #pragma unroll
            for (int j = 0; j < 8; j++) {
                const int col = bn + nb + j*8 + 2*l4;
                float b0 = bias[col], b1 = bias[col + 1];
                __half2 h0 = __floats2half2_rn(acc[i][j][0] + b0, acc[i][j][1] + b1);
                __half2 h1 = __floats2half2_rn(acc[i][j][2] + b0, acc[i][j][3] + b1);
                *(__half2*)&C[(size_t)r0 * HIDDEN + col]       = h0;
                *(__half2*)&C[(size_t)(r0 + 8) * HIDDEN + col] = h1;
            }
        }
    } else {
        // V: store transposed [b][h][d][seq]
        __half* Vt = (__half*)go.out[2];
        #pragma unroll
        for (int i = 0; i < 4; i++) {
            const int r0 = brow + mb + i*16 + g;      // token
            const int b  = r0 >> 11;
            const int s0 = r0 & 2047;
            #pragma unroll
            for (int j = 0; j < 8; j++) {
                const int col = bn + nb + j*8 + 2*l4; // h*128 + d
                const int hh = col >> 7, d = col & 127;
                float b0 = bias[col], b1 = bias[col + 1];
                size_t base0 = ((size_t)(b*NHEADS + hh)*HDIM + d) * SEQ;
                Vt[base0 + s0]            = __float2half_rn(acc[i][j][0] + b0);
                Vt[base0 + SEQ + s0]      = __float2half_rn(acc[i][j][1] + b1);
                Vt[base0 + s0 + 8]        = __float2half_rn(acc[i][j][2] + b0);
                Vt[base0 + SEQ + s0 + 8]  = __float2half_rn(acc[i][j][3] + b1);
            }
        }
    }
}

// ---------------------------------------------------------------------------
// FP16 flash attention (R13 dataflow, halved CTA for 2 CTAs/SM):
// 64 q-rows per block, 128 threads / 4 warps, 128 keys per iter.
// Warp tile 64x32 (wc = warp picks key block for QK / d block for PV).
// Softmax via pmax/psum smem + quad shuffles; P (f16) aliases the K buffer
// (P uses rows 0..63 of the 128-row K tile; all K reads finish before the
// barrier preceding P stores). Single-buffered K/V via cp.async groups:
// CP_WAIT(1) gates QK on K only; CP_WAIT(0) gates PV on V.
// 2 CTAs/SM: regs 239x128 = 30.6K, smem 89.6KB — co-resident CTA hides
// barrier/softmax bubbles (same lever that fixed the GEMM in R9).
// ---------------------------------------------------------------------------
#define AQ  64
#define AKK 128
#define QWH 136                        // row stride in halves (272 B)
#define OQ_B  0
#define OK_B  (AQ*QWH*2)               // 17408  (K tile; P aliases rows 0..63)
#define OV_B  (OK_B + AKK*QWH*2)       // 52224
#define OST_B (OV_B + AKK*QWH*2)       // 87040  (f32 stats)
#define OMX_F 0
#define OL_F  64
#define OPM_F 128                      // pmax[4][64]
#define OPS_F 384                      // psum[4][64]
#define ATT_SMEM (OST_B + 640*4)       // 89600 B  (<= 113KB -> 2 CTAs/SM)

__global__ __launch_bounds__(128, 2) void attn_h16(
    const __half* __restrict__ Q, const __half* __restrict__ K,
    const __half* __restrict__ Vt, const float* __restrict__ mask,
    __half* __restrict__ O)
{
    extern __shared__ char smemc[];
    const uint32_t sbase = smem_u32(smemc);
    __half* sQh = (__half*)(smemc + OQ_B);
    __half* sSh = (__half*)(smemc + OK_B);   // P aliases K rows 0..63
    float* stats = (float*)(smemc + OST_B);
    float* sMx  = stats + OMX_F;
    float* sL   = stats + OL_F;
    float* pmax = stats + OPM_F;
    float* psum = stats + OPS_F;

    const int tid  = threadIdx.x;
    const int lane = tid & 31;
    const int warp = tid >> 5;          // 0..3
    const int g    = lane >> 2;
    const int l4   = lane & 3;
    const int wc   = warp;              // key block (QK) / d block (PV)
    const int cb   = wc * 32;
    const int qt = blockIdx.x, h = blockIdx.y, b = blockIdx.z;
    const size_t base  = (size_t)b * SEQ * HIDDEN + (size_t)h * HDIM;
    const size_t vbase = ((size_t)(b*NHEADS + h)) * HDIM * SEQ;

    const int lrowA = lane & 15;
    const int lcolA = (lane >> 4) * 8;
    const int lrowB = ((lane >> 4) << 3) + (lane & 7);
    const int lcolB = ((lane >> 3) & 1) * 8;

    auto load_k = [&](int kt2) {
        const uint32_t kdst = sbase + OK_B;
        #pragma unroll
        for (int i = 0; i < 16; i++) {
            int it = tid + i*128;
            int r = it >> 4, c = (it & 15) * 8;
            cpa16(kdst + (r*QWH + c)*2,
                  &K[base + (size_t)(kt2*AKK + r)*HIDDEN + c]);
        }
        CP_COMMIT();
    };
    auto load_v = [&](int kt2) {
        const uint32_t vdst = sbase + OV_B;
        #pragma unroll
        for (int i = 0; i < 16; i++) {
            int it = tid + i*128;
            int d = it >> 4, c = (it & 15) * 8;
            cpa16(vdst + (d*QWH + c)*2,
                  &Vt[vbase + (size_t)d*SEQ + kt2*AKK + c]);
        }
        CP_COMMIT();
    };

    // resident Q tile
    for (int it = tid; it < AQ*16; it += 128) {
        int r = it >> 4, c = (it & 15) * 8;
        *(uint4*)&sQh[r*QWH + c] =
            *(const uint4*)&Q[base + (size_t)(qt*AQ + r)*HIDDEN + c];
    }
    if (tid < AQ) { sMx[tid] = -1e30f; sL[tid] = 0.f; }

    float oacc[4][4][4];
    #pragma unroll
    for (int i = 0; i < 4; i++)
        #pragma unroll
        for (int j = 0; j < 4; j++)
            #pragma unroll
            for (int t = 0; t < 4; t++) oacc[i][j][t] = 0.f;

    const uint32_t aQ = sbase + OQ_B + (lrowA * QWH + lcolA) * 2;

    for (int kt = 0; kt < SEQ/AKK; kt++) {      // 16 iterations
        __syncthreads();   // (1) prior PV done: K/P, V buffers + partials free

        load_k(kt);        // group: K
        load_v(kt);        // group: V

        float ml[4][2];
        {
            const float* mrow = &mask[(size_t)b*SEQ + kt*AKK];
            #pragma unroll
            for (int j = 0; j < 4; j++) {
                float2 mv = *(const float2*)&mrow[cb + j*8 + 2*l4];
                ml[j][0] = mv.x * LOG2E;
                ml[j][1] = mv.y * LOG2E;
            }
        }

        CP_WAIT(1);        // K arrived (V may still be in flight)
        __syncthreads();   // (2) K visible to all warps

        // ---- S = Q K^T on warp tile [0:64] x [cb:cb+32]
        float sacc[4][4][4];
        #pragma unroll
        for (int i = 0; i < 4; i++)
            #pragma unroll
            for (int j = 0; j < 4; j++)
                #pragma unroll
                for (int t = 0; t < 4; t++) sacc[i][j][t] = 0.f;

        const uint32_t aK = sbase + OK_B + ((cb + lrowB) * QWH + lcolB) * 2;
        #pragma unroll
        for (int ks = 0; ks < HDIM; ks += 16) {
            unsigned af[4][4], bf[4][2];
            #pragma unroll
            for (int i = 0; i < 4; i++)
                ldsm4(af[i][0], af[i][1], af[i][2], af[i][3],
                      aQ + (i*16*QWH + ks) * 2);
            #pragma unroll
            for (int jp = 0; jp < 2; jp++)
                ldsm4(bf[2*jp][0], bf[2*jp][1], bf[2*jp+1][0], bf[2*jp+1][1],
                      aK + (jp*16*QWH + ks) * 2);
            #pragma unroll
            for (int i = 0; i < 4; i++)
                #pragma unroll
                for (int j = 0; j < 4; j++)
                    mma16(sacc[i][j], af[i], bf[j]);
        }

        // scale + mask (log2 domain)
        #pragma unroll
        for (int i = 0; i < 4; i++)
            #pragma unroll
            for (int j = 0; j < 4; j++) {
                sacc[i][j][0] = sacc[i][j][0]*SCALE2 + ml[j][0];
                sacc[i][j][1] = sacc[i][j][1]*SCALE2 + ml[j][1];
                sacc[i][j][2] = sacc[i][j][2]*SCALE2 + ml[j][0];
                sacc[i][j][3] = sacc[i][j][3]*SCALE2 + ml[j][1];
            }

        // per-row max partials (quad shuffles)
        float mloc[4][2];
        #pragma unroll
        for (int i = 0; i < 4; i++)
            #pragma unroll
            for (int p = 0; p < 2; p++) {
                float m = -1e30f;
                #pragma unroll
                for (int j = 0; j < 4; j++)
                    m = fmaxf(m, fmaxf(sacc[i][j][2*p], sacc[i][j][2*p+1]));
                m = fmaxf(m, __shfl_xor_sync(0xffffffffu, m, 1));
                m = fmaxf(m, __shfl_xor_sync(0xffffffffu, m, 2));
                mloc[i][p] = m;
            }
        if (l4 == 0) {
            #pragma unroll
            for (int i = 0; i < 4; i++)
                #pragma unroll
                for (int p = 0; p < 2; p++)
                    pmax[wc*AQ + i*16 + p*8 + g] = mloc[i][p];
        }
        __syncthreads();   // (3) pmax visible; ALL K reads done (P may overwrite)

        // combine maxes, exponentiate, store f16 P, sum partials
        float mtv[4][2], fv[4][2], lsum[4][2];
        #pragma unroll
        for (int i = 0; i < 4; i++)
            #pragma unroll
            for (int p = 0; p < 2; p++) {
                int r = i*16 + p*8 + g;
                float mo = sMx[r];
                float mt = fmaxf(fmaxf(pmax[r], pmax[AQ+r]),
                                 fmaxf(pmax[2*AQ+r], pmax[3*AQ+r]));
                mt = fmaxf(mo, mt);
                mtv[i][p] = mt;
                fv[i][p]  = ex2(mo - mt);
                lsum[i][p] = 0.f;
            }
        #pragma unroll
        for (int i = 0; i < 4; i++)
            #pragma unroll
            for (int j = 0; j < 4; j++)
                #pragma unroll
                for (int p = 0; p < 2; p++) {
                    float p0 = ex2(sacc[i][j][2*p]   - mtv[i][p]);
                    float p1 = ex2(sacc[i][j][2*p+1] - mtv[i][p]);
                    __half2 ph = __floats2half2_rn(p0, p1);
                    float2 pr = __half22float2(ph);
                    lsum[i][p] += pr.x + pr.y;
                    *(__half2*)&sSh[(i*16 + p*8 + g)*QWH + cb + j*8 + 2*l4] = ph;
                }
        #pragma unroll
        for (int i = 0; i < 4; i++)
            #pragma unroll
            for (int p = 0; p < 2; p++) {
                float l = lsum[i][p];
                l += __shfl_xor_sync(0xffffffffu, l, 1);
                l += __shfl_xor_sync(0xffffffffu, l, 2);
                lsum[i][p] = l;
            }
        if (l4 == 0) {
            #pragma unroll
            for (int i = 0; i < 4; i++)
                #pragma unroll
                for (int p = 0; p < 2; p++)
                    psum[wc*AQ + i*16 + p*8 + g] = lsum[i][p];
        }

        CP_WAIT(0);        // V arrived
        __syncthreads();   // (4) psum + P + V visible

        if (wc == 0 && l4 == 0) {
            #pragma unroll
            for (int i = 0; i < 4; i++)
                #pragma unroll
                for (int p = 0; p < 2; p++) {
                    int r = i*16 + p*8 + g;
                    float ls = psum[r] + psum[AQ+r] + psum[2*AQ+r] + psum[3*AQ+r];
                    sL[r]  = sL[r]*fv[i][p] + ls;
                    sMx[r] = mtv[i][p];
                }
        }

        // rescale O, accumulate P V on warp tile [0:64] x d[cb:cb+32]
        #pragma unroll
        for (int i = 0; i < 4; i++)
            #pragma unroll
            for (int j = 0; j < 4; j++) {
                oacc[i][j][0] *= fv[i][0]; oacc[i][j][1] *= fv[i][0];
                oacc[i][j][2] *= fv[i][1]; oacc[i][j][3] *= fv[i][1];
            }
        const uint32_t aS = sbase + OK_B + (lrowA * QWH + lcolA) * 2;
        const uint32_t aV = sbase + OV_B + ((cb + lrowB) * QWH + lcolB) * 2;
        #pragma unroll
        for (int ks = 0; ks < AKK; ks += 16) {
            unsigned af[4][4], bf[4][2];
            #pragma unroll
            for (int i = 0; i < 4; i++)
                ldsm4(af[i][0], af[i][1], af[i][2], af[i][3],
                      aS + (i*16*QWH + ks) * 2);
            #pragma unroll
            for (int jp = 0; jp < 2; jp++)
                ldsm4(bf[2*jp][0], bf[2*jp][1], bf[2*jp+1][0], bf[2*jp+1][1],
                      aV + (jp*16*QWH + ks) * 2);
            #pragma unroll
            for (int i = 0; i < 4; i++)
                #pragma unroll
                for (int j = 0; j < 4; j++)
                    mma16(oacc[i][j], af[i], bf[j]);
        }
    }

    __syncthreads();       // final sL updates visible

    // normalize + write ctx (f16, [token][hidden] layout)
    #pragma unroll
    for (int i = 0; i < 4; i++) {
        float i0 = 1.f / sL[i*16 + g];
        float i1 = 1.f / sL[i*16 + g + 8];
        #pragma unroll
        for (int j = 0; j < 4; j++) {
            int col = cb + j*8 + 2*l4;
            size_t r0 = base + (size_t)(qt*AQ + i*16 + g    )*HIDDEN + col;
            size_t r1 = base + (size_t)(qt*AQ + i*16 + g + 8)*HIDDEN + col;
            *(__half2*)&O[r0] = __floats2half2_rn(oacc[i][j][0]*i0, oacc[i][j][1]*i0);
            *(__half2*)&O[r1] = __floats2half2_rn(oacc[i][j][2]*i1, oacc[i][j][3]*i1);
        }
    }
}

// ---------------------------------------------------------------------------
extern "C" void kernel_launch(void* const* d_in, const int* in_sizes, int n_in,
                              void* d_out, int out_size) {
    const float* X    = (const float*)d_in[0];
    const float* mask = (const float*)d_in[1];
    const float* Wq   = (const float*)d_in[2];
    const float* bq   = (const float*)d_in[3];
    const float* Wk   = (const float*)d_in[4];
    const float* bk   = (const float*)d_in[5];
    const float* Wv   = (const float*)d_in[6];
    const float* bv   = (const float*)d_in[7];
    const float* Wo   = (const float*)d_in[8];
    const float* bo   = (const float*)d_in[9];
    float* out = (float*)d_out;

    __half *qp, *kp, *vtp, *cp, *xh, *wh;
    cudaGetSymbolAddress((void**)&qp,  g_Qh);
    cudaGetSymbolAddress((void**)&kp,  g_Kh);
    cudaGetSymbolAddress((void**)&vtp, g_Vt);
    cudaGetSymbolAddress((void**)&cp,  g_Ch);
    cudaGetSymbolAddress((void**)&xh,  g_Xh);
    cudaGetSymbolAddress((void**)&wh,  g_Wh);

    const int NX4 = ROWS*HIDDEN/4, NW4 = HIDDEN*HIDDEN/4;
    conv_half_kernel<<<(NX4+255)/256, 256>>>(X, xh, NX4);
    WPtrs ws; ws.w[0] = Wq; ws.w[1] = Wk; ws.w[2] = Wv; ws.w[3] = Wo;
    conv_w4_kernel<<<(4*NW4)/256, 256>>>(ws, wh, NW4);

    cudaFuncSetAttribute(h16_gemm<0>, cudaFuncAttributeMaxDynamicSharedMemorySize, GEMM_SMEM);
    cudaFuncSetAttribute(h16_gemm<1>, cudaFuncAttributeMaxDynamicSharedMemorySize, GEMM_SMEM);

    // Fused QKV GEMM (Wq,Wk,Wv stacked in g_Wh)
    GemmOuts qkv;
    qkv.out[0] = qp;  qkv.out[1] = kp;  qkv.out[2] = vtp;
    qkv.bias[0] = bq; qkv.bias[1] = bk; qkv.bias[2] = bv;
    dim3 qkvgrid(3*HIDDEN/GBN, ROWS/GBM);   // (48, 32)
    h16_gemm<0><<<qkvgrid, 128, GEMM_SMEM>>>(xh, wh, qkv);

    cudaFuncSetAttribute(attn_h16, cudaFuncAttributeMaxDynamicSharedMemorySize, (int)ATT_SMEM);
    dim3 agrid(SEQ/AQ, NHEADS, BATCH);  // (32, 16, 2)
    attn_h16<<<agrid, 128, ATT_SMEM>>>(qp, kp, vtp, mask, cp);

    // Output GEMM: Wo rows at offset 3*H*H, f32 out
    GemmOuts og;
    og.out[0] = out; og.out[1] = out; og.out[2] = out;
    og.bias[0] = bo; og.bias[1] = bo; og.bias[2] = bo;
    dim3 ogrid(HIDDEN/GBN, ROWS/GBM);   // (16, 32)
    h16_gemm<1><<<ogrid, 128, GEMM_SMEM>>>(cp, wh + 3*HIDDEN*HIDDEN, og);
}